// round 4
// baseline (speedup 1.0000x reference)
#include <cuda_runtime.h>

#define B_ 256
#define T_ 1024
#define K_ 128

// Per-batch partial results (__device__ scratch is the sanctioned pattern).
__device__ float g_denom[B_];
__device__ float g_num[B_];

// ---------------------------------------------------------------------------
// Forward algorithm (log-denominator), exponential domain:
//   p_j = exp(alpha_j - C);  s_j = sum_i p_i * E_ij,  E = exp(transitions)
//   p'_j = s_j * exp(emit_j - log p_0);  C += log p_0
// One block per batch row, thread j owns state j, E column j in registers.
// Single shared p-vector, two unconditional barriers per step.
// ---------------------------------------------------------------------------
__global__ void forward_kernel(const float* inp, const float* trans,
                               const int* mask) {
    const int b = blockIdx.x;
    const int j = threadIdx.x;

    __shared__ __align__(16) float pbuf[K_];

    // E column j (coalesced across block, L2-cached across blocks).
    float E[K_];
#pragma unroll
    for (int i = 0; i < K_; i++) E[i] = __expf(trans[i * K_ + j]);

    const float* eb = inp  + (size_t)b * T_ * K_;
    const int*   mb = mask + (size_t)b * T_;

    // t = 0: alpha = emit[0], C = 0, p = exp(alpha)
    pbuf[j] = __expf(eb[j]);
    float C = 0.0f;
    __syncthreads();

    float e_next = eb[K_ + j];          // prefetch t = 1
    int   m_next = mb[1];

    for (int t = 1; t < T_; t++) {
        const float e_cur = e_next;
        const int   mc    = m_next;
        if (t + 1 < T_) {               // prefetch next step
            e_next = eb[(size_t)(t + 1) * K_ + j];
            m_next = mb[t + 1];
        }

        // ---- read phase (everyone reads full p-vector) ----
        const float p0  = pbuf[0];
        const float lp0 = __logf(p0);
        const float4* pv = (const float4*)pbuf;

        float a0 = 0.f, a1 = 0.f, a2 = 0.f, a3 = 0.f;
        float a4 = 0.f, a5 = 0.f, a6 = 0.f, a7 = 0.f;
#pragma unroll
        for (int k = 0; k < 32; k += 2) {
            const float4 u = pv[k];
            a0 = fmaf(u.x, E[4 * k + 0], a0);
            a1 = fmaf(u.y, E[4 * k + 1], a1);
            a2 = fmaf(u.z, E[4 * k + 2], a2);
            a3 = fmaf(u.w, E[4 * k + 3], a3);
            const float4 v = pv[k + 1];
            a4 = fmaf(v.x, E[4 * k + 4], a4);
            a5 = fmaf(v.y, E[4 * k + 5], a5);
            a6 = fmaf(v.z, E[4 * k + 6], a6);
            a7 = fmaf(v.w, E[4 * k + 7], a7);
        }
        const float s = ((a0 + a1) + (a2 + a3)) + ((a4 + a5) + (a6 + a7));
        const float pn = s * __expf(e_cur - lp0);

        __syncthreads();                // reads done before any write
        if (mc) {                       // block-uniform (same mb[t] for all j)
            pbuf[j] = pn;
            C += lp0;
        }
        __syncthreads();                // writes visible before next read
    }

    if (j == 0) {
        float sum = 0.0f;               // fixed order: deterministic
        for (int i = 0; i < K_; i++) sum += pbuf[i];
        g_denom[b] = C + __logf(sum);   // logsumexp(alpha_final)
    }
}

// ---------------------------------------------------------------------------
// Joint (numerator) score. One block per batch, 128 threads strided over t.
// tags read as int32 (JAX x64-disabled: jnp.int64 request materializes int32).
// ---------------------------------------------------------------------------
__global__ void numerator_kernel(const float* inp, const float* trans,
                                 const int* tags, const int* mask) {
    const int b   = blockIdx.x;
    const int tid = threadIdx.x;        // 128
    const int*   tb = tags + (size_t)b * T_;
    const int*   mb = mask + (size_t)b * T_;
    const float* eb = inp  + (size_t)b * T_ * K_;

    float s = 0.0f;
    int msum = 0;
    for (int t = tid; t < T_; t += 128) {
        msum += mb[t];
        if (t < T_ - 1) {
            const int tg  = tb[t]     & (K_ - 1);   // defensive clamp
            const int tg1 = tb[t + 1] & (K_ - 1);
            s += trans[tg * K_ + tg1] * (float)mb[t + 1]
               + eb[(size_t)t * K_ + tg] * (float)mb[t];
        }
    }

    __shared__ float sf[128];
    __shared__ int   si[128];
    sf[tid] = s; si[tid] = msum;
    __syncthreads();
    for (int off = 64; off > 0; off >>= 1) {
        if (tid < off) { sf[tid] += sf[tid + off]; si[tid] += si[tid + off]; }
        __syncthreads();
    }
    if (tid == 0) {
        int last_idx = si[0] - 1;                    // sum(mask) - 1
        if (last_idx < 0)   last_idx = 0;
        if (last_idx >= T_) last_idx = T_ - 1;
        const int lt = tb[last_idx] & (K_ - 1);
        g_num[b] = sf[0]
                 + eb[(size_t)(T_ - 1) * K_ + lt] * (float)mb[T_ - 1];
    }
}

// ---------------------------------------------------------------------------
// Final deterministic reduction: out = sum_b (num_b - denom_b), all fp32.
// ---------------------------------------------------------------------------
__global__ void final_kernel(float* out) {
    __shared__ float sd[B_];
    const int t = threadIdx.x;
    sd[t] = g_num[t] - g_denom[t];
    __syncthreads();
    for (int off = 128; off > 0; off >>= 1) {
        if (t < off) sd[t] += sd[t + off];
        __syncthreads();
    }
    if (t == 0) out[0] = sd[0];
}

// ---------------------------------------------------------------------------
extern "C" void kernel_launch(void* const* d_in, const int* in_sizes, int n_in,
                              void* d_out, int out_size) {
    const float* inp   = (const float*)d_in[0];      // (B,T,K) f32
    const float* trans = (const float*)d_in[1];      // (K,K)   f32
    const int*   tags  = (const int*)d_in[2];        // (B,T)   i32 (JAX x64 off)
    const int*   mask  = (const int*)d_in[3];        // (B,T)   i32
    float* out = (float*)d_out;

    forward_kernel<<<B_, 128>>>(inp, trans, mask);
    numerator_kernel<<<B_, 128>>>(inp, trans, tags, mask);
    final_kernel<<<1, B_>>>(out);
}